// round 15
// baseline (speedup 1.0000x reference)
#include <cuda_runtime.h>
#include <cuda_bf16.h>
#include <cuda_fp16.h>
#include <math.h>
#include <stdint.h>

// Problem constants
#define NATOM 50000
#define MNBR  12
#define AFEA  128
#define NBRF  64
#define NM    (NATOM*MNBR)     // 600000
#define C2A   256
#define EPSV  1e-5f
#define GTILES (NM/96)         // legacy psum sizing (6250 >= GT128)
#define GT128 ((NM + 127)/128) // 4688 gated tiles of 128 rows
#define SCB   1024
#define NSC   ((NM + SCB - 1) / SCB)   // 586
#define GA_ATOMS 32
#define PA2 40
#define P12_BX ((NATOM + 127)/128)     // 391

// ---------------- scratch (device globals) ----------------------------------
__device__ __half g_P1[(size_t)NATOM*C2A];
__device__ __half g_P2[(size_t)NATOM*C2A];
__device__ __half g_gated[(size_t)NM*C2A];
__device__ float  g_psum[(size_t)GTILES*C2A];
__device__ float  g_psq [(size_t)GTILES*C2A];
__device__ float  g_ns[NATOM*AFEA];
__device__ float  g_colsum[C2A];
__device__ float  g_colsq[C2A];
__device__ float  g_cntf;
__device__ int    g_nlive;
__device__ int    g_bcnt[NSC];
__device__ int    g_boff[NSC];
__device__ int    g_pos[NM];
__device__ int    g_live[NM];
__device__ float  g_scale2[AFEA], g_shift2[AFEA];
// pre-split operands
__device__ __align__(16) __nv_bfloat16 g_atHi[(size_t)NATOM*128];
__device__ __align__(16) __nv_bfloat16 g_atLo[(size_t)NATOM*128];
__device__ __align__(16) __nv_bfloat16 g_wspHi[8*4*64*PA2];          // p12 B image
__device__ __align__(16) __nv_bfloat16 g_wspLo[8*4*64*PA2];
__device__ __align__(16) char g_w3Hi[4*8192];   // gated B image, SW128 swizzled
__device__ __align__(16) char g_w3Lo[4*8192];

// ---------------- helpers ----------------------------------------------------
__device__ __forceinline__ void bsplit(float x, __nv_bfloat16& h, __nv_bfloat16& l) {
    h = __float2bfloat16(x);
    l = __float2bfloat16(x - __bfloat162float(h));
}
__device__ __forceinline__ uint32_t bpack(__nv_bfloat16 a, __nv_bfloat16 b) {
    __nv_bfloat162 t(a, b);
    return *(uint32_t*)&t;
}
__device__ __forceinline__ uint32_t swz128(uint32_t o) {
    return o ^ ((o >> 3) & 0x70);
}
__device__ __forceinline__ void mma_bf16(float* c, const uint32_t* a,
                                         uint32_t b0, uint32_t b1) {
    asm volatile(
        "mma.sync.aligned.m16n8k16.row.col.f32.bf16.bf16.f32 "
        "{%0,%1,%2,%3}, {%4,%5,%6,%7}, {%8,%9}, {%0,%1,%2,%3};\n"
        : "+f"(c[0]), "+f"(c[1]), "+f"(c[2]), "+f"(c[3])
        : "r"(a[0]), "r"(a[1]), "r"(a[2]), "r"(a[3]), "r"(b0), "r"(b1));
}
__device__ __forceinline__ void ldsm_x4(uint32_t addr, uint32_t& r0, uint32_t& r1,
                                        uint32_t& r2, uint32_t& r3) {
    asm volatile("ldmatrix.sync.aligned.m8n8.x4.shared.b16 {%0,%1,%2,%3}, [%4];"
                 : "=r"(r0), "=r"(r1), "=r"(r2), "=r"(r3) : "r"(addr));
}
__device__ __forceinline__ float fast_sigmoid(float x) {
    return __fdividef(1.f, 1.f + __expf(-x));
}
__device__ __forceinline__ float fast_softplus(float x) {
    return fmaxf(x, 0.f) + __logf(1.f + __expf(-fabsf(x)));
}

// ---------------- K0: mega kernel — scan1 + atom split + weight splits ------
__global__ __launch_bounds__(256) void mega_split(const float* __restrict__ mask,
                                                  const float* __restrict__ atom,
                                                  const float* __restrict__ W) {
    const int b = blockIdx.x, tid = threadIdx.x;
    if (b < NSC) {
        __shared__ int sw[8];
        const int base = b * SCB;
        int c = 0;
        #pragma unroll
        for (int k = 0; k < 4; k++) {
            int i = base + tid*4 + k;
            if (i < NM) c += (mask[i] != 0.f);
        }
        int v = c;
        #pragma unroll
        for (int off = 16; off > 0; off >>= 1) v += __shfl_xor_sync(0xffffffffu, v, off);
        if ((tid & 31) == 0) sw[tid >> 5] = v;
        __syncthreads();
        if (tid == 0) {
            int t = 0;
            #pragma unroll
            for (int i = 0; i < 8; i++) t += sw[i];
            g_bcnt[b] = t;
        }
    } else if (b < NSC + 6250) {
        size_t t = (size_t)(b - NSC)*256 + tid;
        if (t < (size_t)NATOM*32) {
            float4 v = *(const float4*)&atom[t*4];
            __nv_bfloat16 h0,l0,h1,l1,h2,l2,h3,l3;
            bsplit(v.x, h0, l0); bsplit(v.y, h1, l1);
            bsplit(v.z, h2, l2); bsplit(v.w, h3, l3);
            ((uint2*)g_atHi)[t] = make_uint2(bpack(h0,h1), bpack(h2,h3));
            ((uint2*)g_atLo)[t] = make_uint2(bpack(l0,l1), bpack(l2,l3));
        }
    } else if (b < NSC + 6250 + 128) {
        int t = (b - NSC - 6250)*256 + tid;     // < 32768
        int by = t >> 12, kc = (t >> 10) & 3, n = (t >> 4) & 63, k2 = t & 15;
        int wrow = ((by >= 4) ? 128 : 0) + kc*32 + 2*k2;
        int col  = (by & 3)*64 + n;
        float x0 = W[(size_t)wrow*C2A + col];
        float x1 = W[(size_t)(wrow+1)*C2A + col];
        __nv_bfloat16 h0,l0,h1,l1;
        bsplit(x0, h0, l0); bsplit(x1, h1, l1);
        int o = ((by*4 + kc)*64 + n)*PA2 + 2*k2;
        *(uint32_t*)&g_wspHi[o] = bpack(h0, h1);
        *(uint32_t*)&g_wspLo[o] = bpack(l0, l1);
    } else {
        // W3 swizzled image: t -> (by, n, c8); 8 k-values per thread (16B)
        int t = (b - NSC - 6250 - 128)*256 + tid;   // < 2048
        int by = t >> 9, n = (t >> 3) & 63, c8 = t & 7;
        const float* W3 = W + 256*C2A;
        uint32_t hi[4], lo[4];
        #pragma unroll
        for (int j = 0; j < 4; j++) {
            float x0 = W3[(size_t)(c8*8 + 2*j)  *C2A + by*64 + n];
            float x1 = W3[(size_t)(c8*8 + 2*j+1)*C2A + by*64 + n];
            __nv_bfloat16 h0,l0,h1,l1;
            bsplit(x0, h0, l0); bsplit(x1, h1, l1);
            hi[j] = bpack(h0, h1);
            lo[j] = bpack(l0, l1);
        }
        uint32_t off = swz128((uint32_t)(n*128 + c8*16));
        *(uint4*)&g_w3Hi[by*8192 + off] = make_uint4(hi[0], hi[1], hi[2], hi[3]);
        *(uint4*)&g_w3Lo[by*8192 + off] = make_uint4(lo[0], lo[1], lo[2], lo[3]);
    }
}

// ---------------- K1: top-level scan ----------------------------------------
__global__ __launch_bounds__(1024) void scan2() {
    __shared__ int s[1024];
    const int tid = threadIdx.x;
    int v = (tid < NSC) ? g_bcnt[tid] : 0;
    s[tid] = v;
    __syncthreads();
    for (int off = 1; off < 1024; off <<= 1) {
        int t = (tid >= off) ? s[tid - off] : 0;
        __syncthreads();
        s[tid] += t;
        __syncthreads();
    }
    if (tid < NSC) g_boff[tid] = s[tid] - v;
    if (tid == 1023) {
        g_nlive = s[1023];
        g_cntf  = (float)s[1023];
    }
}

// ---------------- K2: scan3 + p12 (merged; disjoint block ranges) -----------
__global__ __launch_bounds__(256, 4) void scan3_p12(const float* __restrict__ mask) {
    __shared__ __align__(16) __nv_bfloat16 Ahi[128*PA2], Alo[128*PA2];
    __shared__ __align__(16) __nv_bfloat16 Bhi[64*PA2],  Blo[64*PA2];
    __shared__ int sS[256];

    const int bb = blockIdx.x, tid = threadIdx.x;
    if (bb < NSC) {
        const int base = bb * SCB;
        int c = 0;
        #pragma unroll
        for (int k = 0; k < 4; k++) {
            int i = base + tid*4 + k;
            if (i < NM) c += (mask[i] != 0.f);
        }
        sS[tid] = c;
        __syncthreads();
        for (int off = 1; off < 256; off <<= 1) {
            int t = (tid >= off) ? sS[tid - off] : 0;
            __syncthreads();
            sS[tid] += t;
            __syncthreads();
        }
        int p = g_boff[bb] + sS[tid] - c;
        #pragma unroll
        for (int k = 0; k < 4; k++) {
            int i = base + tid*4 + k;
            if (i < NM) {
                g_pos[i] = p;
                if (mask[i] != 0.f) { g_live[p] = i; p++; }
            }
        }
        return;
    }

    // ---- p12 ----
    const int lin = bb - NSC;
    const int bx = lin % P12_BX;
    const int by = lin / P12_BX;              // 0..7
    const int w = tid >> 5, lane = tid & 31, g = lane >> 2, tig = lane & 3;
    const int cb = (by & 3) * 64;
    __half* Cdst = (by >= 4) ? g_P2 : g_P1;
    const int m4 = lane >> 3, lr = lane & 7;

    const uint32_t aHi0 = (uint32_t)__cvta_generic_to_shared(Ahi)
                        + ((w*16 + (m4 & 1)*8 + lr) * PA2 + (m4 >> 1)*8) * 2;
    const uint32_t aLo0 = (uint32_t)__cvta_generic_to_shared(Alo)
                        + ((w*16 + (m4 & 1)*8 + lr) * PA2 + (m4 >> 1)*8) * 2;
    const uint32_t bHi0 = (uint32_t)__cvta_generic_to_shared(Bhi)
                        + (((m4 >> 1)*8 + lr) * PA2 + (m4 & 1)*8) * 2;
    const uint32_t bLo0 = (uint32_t)__cvta_generic_to_shared(Blo)
                        + (((m4 >> 1)*8 + lr) * PA2 + (m4 & 1)*8) * 2;

    float acc[8][4];
    #pragma unroll
    for (int j = 0; j < 8; j++) { acc[j][0]=0.f; acc[j][1]=0.f; acc[j][2]=0.f; acc[j][3]=0.f; }

    for (int kc = 0; kc < 4; kc++) {
        __syncthreads();
        for (int i = tid; i < 1024; i += 256) {
            int a = i >> 9;
            int j = i & 511; int r = j >> 2, u = j & 3;
            int gr = bx*128 + r;
            uint4 v = make_uint4(0, 0, 0, 0);
            if (gr < NATOM) {
                const __nv_bfloat16* src = a ? g_atLo : g_atHi;
                v = ((const uint4*)&src[(size_t)gr*128 + kc*32])[u];
            }
            uint4* dst = (uint4*)(a ? Alo : Ahi);
            dst[r*5 + u] = v;
        }
        {
            const uint4* sh = (const uint4*)&g_wspHi[(size_t)((by*4 + kc)*64) * PA2];
            const uint4* sl = (const uint4*)&g_wspLo[(size_t)((by*4 + kc)*64) * PA2];
            uint4* dh = (uint4*)Bhi;
            uint4* dl = (uint4*)Blo;
            for (int i = tid; i < 320; i += 256) { dh[i] = sh[i]; dl[i] = sl[i]; }
        }
        __syncthreads();

        #pragma unroll
        for (int ks = 0; ks < 2; ks++) {
            const uint32_t koff = ks * 16 * 2;
            uint32_t ah[4], al[4];
            ldsm_x4(aHi0 + koff, ah[0], ah[1], ah[2], ah[3]);
            ldsm_x4(aLo0 + koff, al[0], al[1], al[2], al[3]);
            #pragma unroll
            for (int jp = 0; jp < 4; jp++) {
                const uint32_t boff = (uint32_t)(jp*16*PA2*2) + koff;
                uint32_t bh0, bh1, bh2, bh3, bl0, bl1, bl2, bl3;
                ldsm_x4(bHi0 + boff, bh0, bh1, bh2, bh3);
                ldsm_x4(bLo0 + boff, bl0, bl1, bl2, bl3);
                mma_bf16(acc[2*jp],   ah, bh0, bh1);
                mma_bf16(acc[2*jp],   ah, bl0, bl1);
                mma_bf16(acc[2*jp],   al, bh0, bh1);
                mma_bf16(acc[2*jp+1], ah, bh2, bh3);
                mma_bf16(acc[2*jp+1], ah, bl2, bl3);
                mma_bf16(acc[2*jp+1], al, bh2, bh3);
            }
        }
    }

    const int gr0 = bx*128 + w*16 + g;
    const int gr1 = gr0 + 8;
    #pragma unroll
    for (int j = 0; j < 8; j++) {
        const int c = cb + j*8 + 2*tig;
        if (gr0 < NATOM) {
            __half2 h = __floats2half2_rn(acc[j][0], acc[j][1]);
            *(uint32_t*)&Cdst[(size_t)gr0*C2A + c] = *(uint32_t*)&h;
        }
        if (gr1 < NATOM) {
            __half2 h = __floats2half2_rn(acc[j][2], acc[j][3]);
            *(uint32_t*)&Cdst[(size_t)gr1*C2A + c] = *(uint32_t*)&h;
        }
    }
}

// ---------------- K3: gated GEMM, 128 rows/tile, 4 warps, 32 rows/warp ------
// dyn smem (bytes):
//   Ahi 0..16384, Alo 16384..32768
//   union{ Bhi 32768..40960, Blo 40960..49152 ; CsH (fp16 pitch 68) 32768..50176 }
//   Red 50176..51200, biasS 51200..51456, liveS 51456..51968,
//   nbS 51968..52480, nS 52480..52992
#define SM_TOTAL 52992
__global__ __launch_bounds__(128, 4) void gemm_gated_tc(const float* __restrict__ nbr,
                                                        const float* __restrict__ bfc,
                                                        const int*   __restrict__ idx) {
    extern __shared__ __align__(128) char smraw[];
    char*  AhiB = smraw;
    char*  AloB = smraw + 16384;
    __half* CsH = (__half*)(smraw + 32768);
    float* Red  = (float*)(smraw + 50176);
    float* biasS= (float*)(smraw + 51200);
    int*   liveS= (int*)  (smraw + 51456);
    int*   nbS  = (int*)  (smraw + 51968);
    int*   nS   = (int*)  (smraw + 52480);
    const uint32_t smbase = (uint32_t)__cvta_generic_to_shared(smraw);

    const int tid = threadIdx.x;
    const int bx = blockIdx.x;
    const int nlive = g_nlive;

    if (bx*128 >= nlive) {
        for (int i = tid; i < C2A; i += 128) {
            g_psum[(size_t)bx*C2A + i] = 0.f;
            g_psq [(size_t)bx*C2A + i] = 0.f;
        }
        return;
    }
    const int rem = min(128, nlive - bx*128);

    const int w = tid >> 5, lane = tid & 31, g = lane >> 2, tig = lane & 3;
    const int m4 = lane >> 3, lr = lane & 7;

    // SW128 ldmatrix addressing. A: row = w*32 + gi*16 + (m4&1)*8 + lr, col (m4>>1)*16B
    //                            B: row = (m4>>1)*8 + lr, col (m4&1)*16B
    const uint32_t xorv   = (uint32_t)(lr << 4);
    const uint32_t aCoff0 = (uint32_t)((m4 >> 1) * 16);
    const uint32_t bCoff0 = (uint32_t)((m4 & 1) * 16);
    const uint32_t aRowB  = (uint32_t)((w*32 + (m4 & 1)*8 + lr) * 128);
    const uint32_t aHiB0  = smbase + 0     + aRowB;         // group 0
    const uint32_t aLoB0  = smbase + 16384 + aRowB;
    const uint32_t bRow0  = smbase + 32768 + (uint32_t)(((m4 >> 1)*8 + lr) * 128);

    if (tid < 128) {
        int li = bx*128 + tid;
        int r = (li < nlive) ? g_live[li] : -1;
        liveS[tid] = r;
        nbS[tid] = (r >= 0) ? idx[r] : 0;
        nS[tid]  = (r >= 0) ? r / MNBR : 0;
    }
    __syncthreads();

    // A tile: gather live rows, split, store SW128-swizzled (16B chunks)
    for (int i = tid; i < 128*8; i += 128) {
        int r = i >> 3, ch = i & 7;
        int src = liveS[r];
        float4 v0, v1;
        if (src >= 0) {
            v0 = *(const float4*)&nbr[(size_t)src*64 + ch*8];
            v1 = *(const float4*)&nbr[(size_t)src*64 + ch*8 + 4];
        } else {
            v0 = make_float4(0.f,0.f,0.f,0.f); v1 = v0;
        }
        __nv_bfloat16 h[8], l[8];
        bsplit(v0.x, h[0], l[0]); bsplit(v0.y, h[1], l[1]);
        bsplit(v0.z, h[2], l[2]); bsplit(v0.w, h[3], l[3]);
        bsplit(v1.x, h[4], l[4]); bsplit(v1.y, h[5], l[5]);
        bsplit(v1.z, h[6], l[6]); bsplit(v1.w, h[7], l[7]);
        uint32_t off = swz128((uint32_t)(r*128 + ch*16));
        *(uint4*)(AhiB + off) = make_uint4(bpack(h[0],h[1]), bpack(h[2],h[3]),
                                           bpack(h[4],h[5]), bpack(h[6],h[7]));
        *(uint4*)(AloB + off) = make_uint4(bpack(l[0],l[1]), bpack(l[2],l[3]),
                                           bpack(l[4],l[5]), bpack(l[6],l[7]));
    }

    const int q = tid & 15;
    const int rsub = tid >> 4;   // 0..7

    for (int by = 0; by < 4; by++) {
        __syncthreads();   // prior epilogue done; Cs/B region free
        {   // stage B: 16B copies of swizzled image (8KB hi + 8KB lo)
            const uint4* sh = (const uint4*)(g_w3Hi + by*8192);
            const uint4* sl = (const uint4*)(g_w3Lo + by*8192);
            uint4* dh = (uint4*)(smraw + 32768);
            uint4* dl = (uint4*)(smraw + 40960);
            #pragma unroll
            for (int i = 0; i < 4; i++) {
                int o = tid + i*128;
                dh[o] = sh[o]; dl[o] = sl[o];
            }
        }
        if (tid < 16)
            *(float4*)&biasS[tid*4] = *(const float4*)&bfc[by*64 + tid*4];
        __syncthreads();

        float acc[2][8][4];
        #pragma unroll
        for (int gi = 0; gi < 2; gi++)
            #pragma unroll
            for (int j = 0; j < 8; j++) {
                acc[gi][j][0]=0.f; acc[gi][j][1]=0.f; acc[gi][j][2]=0.f; acc[gi][j][3]=0.f;
            }

        #pragma unroll
        for (int ks = 0; ks < 4; ks++) {
            const uint32_t kxa = (aCoff0 + ks*32) ^ xorv;
            const uint32_t kxb = (bCoff0 + ks*32) ^ xorv;
            uint32_t ah0[4], al0[4], ah1[4], al1[4];
            ldsm_x4(aHiB0 + kxa,        ah0[0], ah0[1], ah0[2], ah0[3]);
            ldsm_x4(aLoB0 + kxa,        al0[0], al0[1], al0[2], al0[3]);
            ldsm_x4(aHiB0 + 2048 + kxa, ah1[0], ah1[1], ah1[2], ah1[3]);   // +16 rows
            ldsm_x4(aLoB0 + 2048 + kxa, al1[0], al1[1], al1[2], al1[3]);
            #pragma unroll
            for (int jp = 0; jp < 4; jp++) {
                const uint32_t bb = bRow0 + (uint32_t)(jp*2048) + kxb;
                uint32_t bh0, bh1, bh2, bh3, bl0, bl1, bl2, bl3;
                ldsm_x4(bb,        bh0, bh1, bh2, bh3);
                ldsm_x4(bb + 8192, bl0, bl1, bl2, bl3);
                mma_bf16(acc[0][2*jp],   ah0, bh0, bh1);
                mma_bf16(acc[0][2*jp],   ah0, bl0, bl1);
                mma_bf16(acc[0][2*jp],   al0, bh0, bh1);
                mma_bf16(acc[0][2*jp+1], ah0, bh2, bh3);
                mma_bf16(acc[0][2*jp+1], ah0, bl2, bl3);
                mma_bf16(acc[0][2*jp+1], al0, bh2, bh3);
                mma_bf16(acc[1][2*jp],   ah1, bh0, bh1);
                mma_bf16(acc[1][2*jp],   ah1, bl0, bl1);
                mma_bf16(acc[1][2*jp],   al1, bh0, bh1);
                mma_bf16(acc[1][2*jp+1], ah1, bh2, bh3);
                mma_bf16(acc[1][2*jp+1], ah1, bl2, bl3);
                mma_bf16(acc[1][2*jp+1], al1, bh2, bh3);
            }
        }

        __syncthreads();   // B reads done; region becomes CsH
        #pragma unroll
        for (int gi = 0; gi < 2; gi++) {
            const int rl0 = w*32 + gi*16 + g, rl1 = rl0 + 8;
            #pragma unroll
            for (int j = 0; j < 8; j++) {
                const int c = j*8 + 2*tig;
                __half2 h0 = __floats2half2_rn(acc[gi][j][0], acc[gi][j][1]);
                __half2 h1 = __floats2half2_rn(acc[gi][j][2], acc[gi][j][3]);
                *(__half2*)&CsH[rl0*68 + c] = h0;
                *(__half2*)&CsH[rl1*68 + c] = h1;
            }
        }
        __syncthreads();

        float s0=0.f,s1=0.f,s2=0.f,s3=0.f, q0=0.f,q1=0.f,q2=0.f,q3=0.f;
        #pragma unroll
        for (int it = 0; it < 16; it++) {
            const int r = it*8 + rsub;
            if (r < rem) {
                uint2 uc = *(const uint2*)&CsH[r*68 + q*4];
                float2 c01 = __half22float2(*(__half2*)&uc.x);
                float2 c23 = __half22float2(*(__half2*)&uc.y);
                uint2 u1 = *(const uint2*)&g_P1[(size_t)nS[r]*C2A + by*64 + q*4];
                uint2 u2 = *(const uint2*)&g_P2[(size_t)nbS[r]*C2A + by*64 + q*4];
                float2 p1a = __half22float2(*(__half2*)&u1.x);
                float2 p1b = __half22float2(*(__half2*)&u1.y);
                float2 p2a = __half22float2(*(__half2*)&u2.x);
                float2 p2b = __half22float2(*(__half2*)&u2.y);
                float4 bb = *(const float4*)&biasS[q*4];
                float4 v;
                v.x = c01.x + p1a.x + p2a.x + bb.x;
                v.y = c01.y + p1a.y + p2a.y + bb.y;
                v.z = c23.x + p1b.x + p2b.x + bb.z;
                v.w = c23.y + p1b.y + p2b.y + bb.w;
                __half2 h01 = __floats2half2_rn(v.x, v.y);
                __half2 h23 = __floats2half2_rn(v.z, v.w);
                *(uint2*)&g_gated[((size_t)(bx*128 + r))*C2A + by*64 + q*4] =
                    make_uint2(*(uint32_t*)&h01, *(uint32_t*)&h23);
                s0 += v.x; s1 += v.y; s2 += v.z; s3 += v.w;
                q0 += v.x*v.x; q1 += v.y*v.y; q2 += v.z*v.z; q3 += v.w*v.w;
            }
        }
        s0 += __shfl_xor_sync(0xffffffffu, s0, 16);
        s1 += __shfl_xor_sync(0xffffffffu, s1, 16);
        s2 += __shfl_xor_sync(0xffffffffu, s2, 16);
        s3 += __shfl_xor_sync(0xffffffffu, s3, 16);
        q0 += __shfl_xor_sync(0xffffffffu, q0, 16);
        q1 += __shfl_xor_sync(0xffffffffu, q1, 16);
        q2 += __shfl_xor_sync(0xffffffffu, q2, 16);
        q3 += __shfl_xor_sync(0xffffffffu, q3, 16);

        if (lane < 16) {
            float* d = &Red[w*64 + lane*4];
            d[0]=s0; d[1]=s1; d[2]=s2; d[3]=s3;
        }
        __syncthreads();
        if (tid < 64) {
            float ts = 0.f;
            #pragma unroll
            for (int w2 = 0; w2 < 4; w2++) ts += Red[w2*64 + tid];
            g_psum[(size_t)bx*C2A + by*64 + tid] = ts;
        }
        __syncthreads();
        if (lane < 16) {
            float* d = &Red[w*64 + lane*4];
            d[0]=q0; d[1]=q1; d[2]=q2; d[3]=q3;
        }
        __syncthreads();
        if (tid < 64) {
            float tq = 0.f;
            #pragma unroll
            for (int w2 = 0; w2 < 4; w2++) tq += Red[w2*64 + tid];
            g_psq[(size_t)bx*C2A + by*64 + tid] = tq;
        }
    }
}

// ---------------- K4: reduce partials -> column sums ------------------------
__global__ __launch_bounds__(256) void reduce_cols() {
    __shared__ float sm[256];
    const int b = blockIdx.x, tid = threadIdx.x;
    float s = 0.f;
    if (b < 256) {
        for (int i = tid; i < GT128; i += 256) s += g_psum[(size_t)i * C2A + b];
    } else {
        int c = b - 256;
        for (int i = tid; i < GT128; i += 256) s += g_psq[(size_t)i * C2A + c];
    }
    sm[tid] = s; __syncthreads();
    for (int off = 128; off > 0; off >>= 1) {
        if (tid < off) sm[tid] += sm[tid + off];
        __syncthreads();
    }
    if (tid == 0) {
        if (b < 256) g_colsum[b] = sm[0];
        else         g_colsq[b - 256] = sm[0];
    }
}

// ---------------- K5: BN1-apply + gate + per-atom sum (32 atoms/block) ------
__global__ __launch_bounds__(256) void gate_apply(const float* __restrict__ gamma1,
                                                  const float* __restrict__ beta1) {
    __shared__ float s1s[C2A], s1b[C2A];
    __shared__ int sA[GA_ATOMS + 1];
    const int tid = threadIdx.x;
    const int bx = blockIdx.x;

    {
        float cnt = g_cntf;
        float mean = g_colsum[tid] / cnt;
        float var  = g_colsq[tid] / cnt - mean * mean;
        float sc   = rsqrtf(var + EPSV) * gamma1[tid];
        s1s[tid] = sc;
        s1b[tid] = beta1[tid] - mean * sc;
    }
    if (tid <= GA_ATOMS) {
        int i9 = (bx*GA_ATOMS + tid) * MNBR;
        sA[tid] = (i9 < NM) ? g_pos[i9] : g_nlive;
    }
    __syncthreads();

    const int c4 = (tid & 31) * 4;   // col quad
    const int ag = tid >> 5;         // 0..7
    const float sf0 = s1s[c4],   sf1 = s1s[c4+1], sf2 = s1s[c4+2], sf3 = s1s[c4+3];
    const float bf0 = s1b[c4],   bf1 = s1b[c4+1], bf2 = s1b[c4+2], bf3 = s1b[c4+3];
    const float sc0 = s1s[128+c4], sc1 = s1s[128+c4+1], sc2v = s1s[128+c4+2], sc3 = s1s[128+c4+3];
    const float bc0 = s1b[128+c4], bc1 = s1b[128+c4+1], bc2 = s1b[128+c4+2], bc3 = s1b[128+c4+3];

    #pragma unroll
    for (int aa = 0; aa < GA_ATOMS/8; aa++) {
        const int a = aa*8 + ag;
        const int atom = bx*GA_ATOMS + a;
        if (atom < NATOM) {
            const int start = sA[a], end = sA[a+1];
            float sx = 0.f, sy = 0.f, sz = 0.f, sw2 = 0.f;
            for (int row = start; row < end; row++) {
                uint2 uf = *(const uint2*)&g_gated[(size_t)row*C2A + c4];
                uint2 ucv = *(const uint2*)&g_gated[(size_t)row*C2A + 128 + c4];
                float2 fa = __half22float2(*(__half2*)&uf.x);
                float2 fb = __half22float2(*(__half2*)&uf.y);
                float2 ca = __half22float2(*(__half2*)&ucv.x);
                float2 cb = __half22float2(*(__half2*)&ucv.y);
                sx  += fast_sigmoid(fa.x*sf0 + bf0) * fast_softplus(ca.x*sc0 + bc0);
                sy  += fast_sigmoid(fa.y*sf1 + bf1) * fast_softplus(ca.y*sc1 + bc1);
                sz  += fast_sigmoid(fb.x*sf2 + bf2) * fast_softplus(cb.x*sc2v + bc2);
                sw2 += fast_sigmoid(fb.y*sf3 + bf3) * fast_softplus(cb.y*sc3 + bc3);
            }
            *(float4*)&g_ns[(size_t)atom*AFEA + c4] = make_float4(sx, sy, sz, sw2);
        }
    }
}

// ---------------- K6: BN2 stats + affine ------------------------------------
__global__ __launch_bounds__(256) void reduce2(const float* __restrict__ gamma2,
                                               const float* __restrict__ beta2) {
    __shared__ float ss[256], sq[256];
    const int c = blockIdx.x, tid = threadIdx.x;
    float s = 0.f, q = 0.f;
    for (int r = tid; r < NATOM; r += 256) {
        float v = g_ns[(size_t)r * AFEA + c];
        s += v; q += v * v;
    }
    ss[tid] = s; sq[tid] = q; __syncthreads();
    for (int off = 128; off > 0; off >>= 1) {
        if (tid < off) { ss[tid] += ss[tid + off]; sq[tid] += sq[tid + off]; }
        __syncthreads();
    }
    if (tid == 0) {
        float mean = ss[0] / (float)NATOM;
        float var  = sq[0] / (float)NATOM - mean * mean;
        float sc   = rsqrtf(var + EPSV) * gamma2[c];
        g_scale2[c] = sc;
        g_shift2[c] = beta2[c] - mean * sc;
    }
}

// ---------------- K7: out = softplus(atom + BN2(nbr_sumed)) -----------------
__global__ __launch_bounds__(256) void out_k(const float* __restrict__ atom,
                                             float* __restrict__ out) {
    int i = blockIdx.x * 256 + threadIdx.x;
    if (i < NATOM * AFEA) {
        int c = i & 127;
        float v = atom[i] + g_ns[i] * g_scale2[c] + g_shift2[c];
        out[i] = fmaxf(v, 0.f) + __logf(1.f + __expf(-fabsf(v)));
    }
}

// ---------------- launch ----------------------------------------------------
extern "C" void kernel_launch(void* const* d_in, const int* in_sizes, int n_in,
                              void* d_out, int out_size) {
    const float* atom  = (const float*)d_in[0];
    const float* nbr   = (const float*)d_in[1];
    const int*   idx   = (const int*)  d_in[2];
    const float* mask  = (const float*)d_in[3];
    const float* W     = (const float*)d_in[4];
    const float* bfc   = (const float*)d_in[5];
    const float* g1    = (const float*)d_in[6];
    const float* b1    = (const float*)d_in[7];
    const float* g2    = (const float*)d_in[8];
    const float* b2    = (const float*)d_in[9];
    float* out = (float*)d_out;

    cudaFuncSetAttribute(gemm_gated_tc, cudaFuncAttributeMaxDynamicSharedMemorySize, SM_TOTAL);

    mega_split   <<<NSC + 6250 + 128 + 8, 256>>>(mask, atom, W);         // 0
    scan2        <<<1, 1024>>>();                                        // 1
    scan3_p12    <<<NSC + P12_BX*8, 256>>>(mask);                        // 2
    gemm_gated_tc<<<GT128, 128, SM_TOTAL>>>(nbr, bfc, idx);              // 3 (profiled)
    reduce_cols  <<<512, 256>>>();                                       // 4
    gate_apply   <<<(NATOM + GA_ATOMS - 1)/GA_ATOMS, 256>>>(g1, b1);     // 5
    reduce2      <<<AFEA, 256>>>(g2, b2);                                // 6
    out_k        <<<(NATOM * AFEA + 255) / 256, 256>>>(atom, out);       // 7
}

// round 17
// speedup vs baseline: 1.5435x; 1.5435x over previous
#include <cuda_runtime.h>
#include <cuda_bf16.h>
#include <cuda_fp16.h>
#include <math.h>
#include <stdint.h>

// Problem constants
#define NATOM 50000
#define MNBR  12
#define AFEA  128
#define NBRF  64
#define NM    (NATOM*MNBR)     // 600000
#define C2A   256
#define EPSV  1e-5f
#define GTILES (NM/96)         // 6250 row tiles of 96
#define SCB   1024
#define NSC   ((NM + SCB - 1) / SCB)   // 586
#define GA_ATOMS 32
#define PA2 40
#define P12_BX ((NATOM + 127)/128)     // 391

// ---------------- scratch (device globals) ----------------------------------
__device__ __half g_P1[(size_t)NATOM*C2A];
__device__ __half g_P2[(size_t)NATOM*C2A];
__device__ __half g_gated[(size_t)NM*C2A];
__device__ float  g_psum[(size_t)GTILES*C2A];
__device__ float  g_psq [(size_t)GTILES*C2A];
__device__ float  g_ns[NATOM*AFEA];
__device__ float  g_colsum[C2A];
__device__ float  g_colsq[C2A];
__device__ float  g_cntf;
__device__ int    g_nlive;
__device__ int    g_bcnt[NSC];
__device__ int    g_boff[NSC];
__device__ int    g_pos[NM];
__device__ int    g_live[NM];
__device__ float  g_scale2[AFEA], g_shift2[AFEA];
// pre-split operands
__device__ __align__(16) __nv_bfloat16 g_atHi[(size_t)NATOM*128];
__device__ __align__(16) __nv_bfloat16 g_atLo[(size_t)NATOM*128];
__device__ __align__(16) __nv_bfloat16 g_wspHi[8*4*64*PA2];          // p12 B image
__device__ __align__(16) __nv_bfloat16 g_wspLo[8*4*64*PA2];
__device__ __align__(16) char g_w3Hi[4*8192];   // gated B image, SW128 swizzled
__device__ __align__(16) char g_w3Lo[4*8192];

// ---------------- helpers ----------------------------------------------------
__device__ __forceinline__ void bsplit(float x, __nv_bfloat16& h, __nv_bfloat16& l) {
    h = __float2bfloat16(x);
    l = __float2bfloat16(x - __bfloat162float(h));
}
__device__ __forceinline__ uint32_t bpack(__nv_bfloat16 a, __nv_bfloat16 b) {
    __nv_bfloat162 t(a, b);
    return *(uint32_t*)&t;
}
__device__ __forceinline__ uint32_t swz128(uint32_t o) {
    return o ^ ((o >> 3) & 0x70);
}
__device__ __forceinline__ void mma_bf16(float* c, const uint32_t* a,
                                         uint32_t b0, uint32_t b1) {
    asm volatile(
        "mma.sync.aligned.m16n8k16.row.col.f32.bf16.bf16.f32 "
        "{%0,%1,%2,%3}, {%4,%5,%6,%7}, {%8,%9}, {%0,%1,%2,%3};\n"
        : "+f"(c[0]), "+f"(c[1]), "+f"(c[2]), "+f"(c[3])
        : "r"(a[0]), "r"(a[1]), "r"(a[2]), "r"(a[3]), "r"(b0), "r"(b1));
}
__device__ __forceinline__ void ldsm_x4(uint32_t addr, uint32_t& r0, uint32_t& r1,
                                        uint32_t& r2, uint32_t& r3) {
    asm volatile("ldmatrix.sync.aligned.m8n8.x4.shared.b16 {%0,%1,%2,%3}, [%4];"
                 : "=r"(r0), "=r"(r1), "=r"(r2), "=r"(r3) : "r"(addr));
}
__device__ __forceinline__ float fast_sigmoid(float x) {
    return __fdividef(1.f, 1.f + __expf(-x));
}
__device__ __forceinline__ float fast_softplus(float x) {
    return fmaxf(x, 0.f) + __logf(1.f + __expf(-fabsf(x)));
}

// ---------------- K0: mega kernel — scan1 + atom split + weight splits ------
__global__ __launch_bounds__(256) void mega_split(const float* __restrict__ mask,
                                                  const float* __restrict__ atom,
                                                  const float* __restrict__ W) {
    const int b = blockIdx.x, tid = threadIdx.x;
    if (b < NSC) {
        __shared__ int sw[8];
        const int base = b * SCB;
        int c = 0;
        #pragma unroll
        for (int k = 0; k < 4; k++) {
            int i = base + tid*4 + k;
            if (i < NM) c += (mask[i] != 0.f);
        }
        int v = c;
        #pragma unroll
        for (int off = 16; off > 0; off >>= 1) v += __shfl_xor_sync(0xffffffffu, v, off);
        if ((tid & 31) == 0) sw[tid >> 5] = v;
        __syncthreads();
        if (tid == 0) {
            int t = 0;
            #pragma unroll
            for (int i = 0; i < 8; i++) t += sw[i];
            g_bcnt[b] = t;
        }
    } else if (b < NSC + 6250) {
        size_t t = (size_t)(b - NSC)*256 + tid;
        if (t < (size_t)NATOM*32) {
            float4 v = *(const float4*)&atom[t*4];
            __nv_bfloat16 h0,l0,h1,l1,h2,l2,h3,l3;
            bsplit(v.x, h0, l0); bsplit(v.y, h1, l1);
            bsplit(v.z, h2, l2); bsplit(v.w, h3, l3);
            ((uint2*)g_atHi)[t] = make_uint2(bpack(h0,h1), bpack(h2,h3));
            ((uint2*)g_atLo)[t] = make_uint2(bpack(l0,l1), bpack(l2,l3));
        }
    } else if (b < NSC + 6250 + 128) {
        int t = (b - NSC - 6250)*256 + tid;     // < 32768
        int by = t >> 12, kc = (t >> 10) & 3, n = (t >> 4) & 63, k2 = t & 15;
        int wrow = ((by >= 4) ? 128 : 0) + kc*32 + 2*k2;
        int col  = (by & 3)*64 + n;
        float x0 = W[(size_t)wrow*C2A + col];
        float x1 = W[(size_t)(wrow+1)*C2A + col];
        __nv_bfloat16 h0,l0,h1,l1;
        bsplit(x0, h0, l0); bsplit(x1, h1, l1);
        int o = ((by*4 + kc)*64 + n)*PA2 + 2*k2;
        *(uint32_t*)&g_wspHi[o] = bpack(h0, h1);
        *(uint32_t*)&g_wspLo[o] = bpack(l0, l1);
    } else {
        // W3 swizzled image: t -> (by, n, c8); 8 k-values per thread (16B)
        int t = (b - NSC - 6250 - 128)*256 + tid;   // < 2048
        int by = t >> 9, n = (t >> 3) & 63, c8 = t & 7;
        const float* W3 = W + 256*C2A;
        uint32_t hi[4], lo[4];
        #pragma unroll
        for (int j = 0; j < 4; j++) {
            float x0 = W3[(size_t)(c8*8 + 2*j)  *C2A + by*64 + n];
            float x1 = W3[(size_t)(c8*8 + 2*j+1)*C2A + by*64 + n];
            __nv_bfloat16 h0,l0,h1,l1;
            bsplit(x0, h0, l0); bsplit(x1, h1, l1);
            hi[j] = bpack(h0, h1);
            lo[j] = bpack(l0, l1);
        }
        uint32_t off = swz128((uint32_t)(n*128 + c8*16));
        *(uint4*)&g_w3Hi[by*8192 + off] = make_uint4(hi[0], hi[1], hi[2], hi[3]);
        *(uint4*)&g_w3Lo[by*8192 + off] = make_uint4(lo[0], lo[1], lo[2], lo[3]);
    }
}

// ---------------- K1: top-level scan ----------------------------------------
__global__ __launch_bounds__(1024) void scan2() {
    __shared__ int s[1024];
    const int tid = threadIdx.x;
    int v = (tid < NSC) ? g_bcnt[tid] : 0;
    s[tid] = v;
    __syncthreads();
    for (int off = 1; off < 1024; off <<= 1) {
        int t = (tid >= off) ? s[tid - off] : 0;
        __syncthreads();
        s[tid] += t;
        __syncthreads();
    }
    if (tid < NSC) g_boff[tid] = s[tid] - v;
    if (tid == 1023) {
        g_nlive = s[1023];
        g_cntf  = (float)s[1023];
    }
}

// ---------------- K2: scan3 + p12 (merged; disjoint block ranges) -----------
__global__ __launch_bounds__(256, 4) void scan3_p12(const float* __restrict__ mask) {
    __shared__ __align__(16) __nv_bfloat16 Ahi[128*PA2], Alo[128*PA2];
    __shared__ __align__(16) __nv_bfloat16 Bhi[64*PA2],  Blo[64*PA2];
    __shared__ int sS[256];

    const int bb = blockIdx.x, tid = threadIdx.x;
    if (bb < NSC) {
        const int base = bb * SCB;
        int c = 0;
        #pragma unroll
        for (int k = 0; k < 4; k++) {
            int i = base + tid*4 + k;
            if (i < NM) c += (mask[i] != 0.f);
        }
        sS[tid] = c;
        __syncthreads();
        for (int off = 1; off < 256; off <<= 1) {
            int t = (tid >= off) ? sS[tid - off] : 0;
            __syncthreads();
            sS[tid] += t;
            __syncthreads();
        }
        int p = g_boff[bb] + sS[tid] - c;
        #pragma unroll
        for (int k = 0; k < 4; k++) {
            int i = base + tid*4 + k;
            if (i < NM) {
                g_pos[i] = p;
                if (mask[i] != 0.f) { g_live[p] = i; p++; }
            }
        }
        return;
    }

    // ---- p12 ----
    const int lin = bb - NSC;
    const int bx = lin % P12_BX;
    const int by = lin / P12_BX;              // 0..7
    const int w = tid >> 5, lane = tid & 31, g = lane >> 2, tig = lane & 3;
    const int cb = (by & 3) * 64;
    __half* Cdst = (by >= 4) ? g_P2 : g_P1;
    const int m4 = lane >> 3, lr = lane & 7;

    const uint32_t aHi0 = (uint32_t)__cvta_generic_to_shared(Ahi)
                        + ((w*16 + (m4 & 1)*8 + lr) * PA2 + (m4 >> 1)*8) * 2;
    const uint32_t aLo0 = (uint32_t)__cvta_generic_to_shared(Alo)
                        + ((w*16 + (m4 & 1)*8 + lr) * PA2 + (m4 >> 1)*8) * 2;
    const uint32_t bHi0 = (uint32_t)__cvta_generic_to_shared(Bhi)
                        + (((m4 >> 1)*8 + lr) * PA2 + (m4 & 1)*8) * 2;
    const uint32_t bLo0 = (uint32_t)__cvta_generic_to_shared(Blo)
                        + (((m4 >> 1)*8 + lr) * PA2 + (m4 & 1)*8) * 2;

    float acc[8][4];
    #pragma unroll
    for (int j = 0; j < 8; j++) { acc[j][0]=0.f; acc[j][1]=0.f; acc[j][2]=0.f; acc[j][3]=0.f; }

    for (int kc = 0; kc < 4; kc++) {
        __syncthreads();
        for (int i = tid; i < 1024; i += 256) {
            int a = i >> 9;
            int j = i & 511; int r = j >> 2, u = j & 3;
            int gr = bx*128 + r;
            uint4 v = make_uint4(0, 0, 0, 0);
            if (gr < NATOM) {
                const __nv_bfloat16* src = a ? g_atLo : g_atHi;
                v = ((const uint4*)&src[(size_t)gr*128 + kc*32])[u];
            }
            uint4* dst = (uint4*)(a ? Alo : Ahi);
            dst[r*5 + u] = v;
        }
        {
            const uint4* sh = (const uint4*)&g_wspHi[(size_t)((by*4 + kc)*64) * PA2];
            const uint4* sl = (const uint4*)&g_wspLo[(size_t)((by*4 + kc)*64) * PA2];
            uint4* dh = (uint4*)Bhi;
            uint4* dl = (uint4*)Blo;
            for (int i = tid; i < 320; i += 256) { dh[i] = sh[i]; dl[i] = sl[i]; }
        }
        __syncthreads();

        #pragma unroll
        for (int ks = 0; ks < 2; ks++) {
            const uint32_t koff = ks * 16 * 2;
            uint32_t ah[4], al[4];
            ldsm_x4(aHi0 + koff, ah[0], ah[1], ah[2], ah[3]);
            ldsm_x4(aLo0 + koff, al[0], al[1], al[2], al[3]);
            #pragma unroll
            for (int jp = 0; jp < 4; jp++) {
                const uint32_t boff = (uint32_t)(jp*16*PA2*2) + koff;
                uint32_t bh0, bh1, bh2, bh3, bl0, bl1, bl2, bl3;
                ldsm_x4(bHi0 + boff, bh0, bh1, bh2, bh3);
                ldsm_x4(bLo0 + boff, bl0, bl1, bl2, bl3);
                mma_bf16(acc[2*jp],   ah, bh0, bh1);
                mma_bf16(acc[2*jp],   ah, bl0, bl1);
                mma_bf16(acc[2*jp],   al, bh0, bh1);
                mma_bf16(acc[2*jp+1], ah, bh2, bh3);
                mma_bf16(acc[2*jp+1], ah, bl2, bl3);
                mma_bf16(acc[2*jp+1], al, bh2, bh3);
            }
        }
    }

    const int gr0 = bx*128 + w*16 + g;
    const int gr1 = gr0 + 8;
    #pragma unroll
    for (int j = 0; j < 8; j++) {
        const int c = cb + j*8 + 2*tig;
        if (gr0 < NATOM) {
            __half2 h = __floats2half2_rn(acc[j][0], acc[j][1]);
            *(uint32_t*)&Cdst[(size_t)gr0*C2A + c] = *(uint32_t*)&h;
        }
        if (gr1 < NATOM) {
            __half2 h = __floats2half2_rn(acc[j][2], acc[j][3]);
            *(uint32_t*)&Cdst[(size_t)gr1*C2A + c] = *(uint32_t*)&h;
        }
    }
}

// ---------------- K3: gated GEMM, SW128 smem, fp16 Cs, 5 blocks/SM (R14) ----
#define SM_TOTAL 43904
__global__ __launch_bounds__(192, 5) void gemm_gated_tc(const float* __restrict__ nbr,
                                                        const float* __restrict__ bfc,
                                                        const int*   __restrict__ idx) {
    extern __shared__ __align__(128) char smraw[];
    char*  AhiB = smraw;
    char*  AloB = smraw + 12288;
    __half* CsH = (__half*)(smraw + 24576);
    float* Red  = (float*)(smraw + 40960);
    float* biasS= (float*)(smraw + 42496);
    int*   liveS= (int*)  (smraw + 42752);
    int*   nbS  = (int*)  (smraw + 43136);
    int*   nS   = (int*)  (smraw + 43520);
    const uint32_t smbase = (uint32_t)__cvta_generic_to_shared(smraw);

    const int tid = threadIdx.x;
    const int bx = blockIdx.x;
    const int nlive = g_nlive;

    if (bx*96 >= nlive) {
        for (int i = tid; i < C2A; i += 192) {
            g_psum[(size_t)bx*C2A + i] = 0.f;
            g_psq [(size_t)bx*C2A + i] = 0.f;
        }
        return;
    }
    const int rem = min(96, nlive - bx*96);

    const int w = tid >> 5, lane = tid & 31, g = lane >> 2, tig = lane & 3;
    const int m4 = lane >> 3, lr = lane & 7;

    const uint32_t xorv   = (uint32_t)(lr << 4);
    const uint32_t aCoff0 = (uint32_t)((m4 >> 1) * 16);
    const uint32_t bCoff0 = (uint32_t)((m4 & 1) * 16);
    const uint32_t aRow   = (uint32_t)((w*16 + (m4 & 1)*8 + lr) * 128);
    const uint32_t aHiB0  = smbase + 0     + aRow;
    const uint32_t aLoB0  = smbase + 12288 + aRow;
    const uint32_t bRow0  = smbase + 24576 + (uint32_t)(((m4 >> 1)*8 + lr) * 128);

    if (tid < 96) {
        int li = bx*96 + tid;
        int r = (li < nlive) ? g_live[li] : -1;
        liveS[tid] = r;
        nbS[tid] = (r >= 0) ? idx[r] : 0;
        nS[tid]  = (r >= 0) ? r / MNBR : 0;
    }
    __syncthreads();

    for (int i = tid; i < 96*8; i += 192) {
        int r = i >> 3, ch = i & 7;
        int src = liveS[r];
        float4 v0, v1;
        if (src >= 0) {
            v0 = *(const float4*)&nbr[(size_t)src*64 + ch*8];
            v1 = *(const float4*)&nbr[(size_t)src*64 + ch*8 + 4];
        } else {
            v0 = make_float4(0.f,0.f,0.f,0.f); v1 = v0;
        }
        __nv_bfloat16 h[8], l[8];
        bsplit(v0.x, h[0], l[0]); bsplit(v0.y, h[1], l[1]);
        bsplit(v0.z, h[2], l[2]); bsplit(v0.w, h[3], l[3]);
        bsplit(v1.x, h[4], l[4]); bsplit(v1.y, h[5], l[5]);
        bsplit(v1.z, h[6], l[6]); bsplit(v1.w, h[7], l[7]);
        uint32_t off = swz128((uint32_t)(r*128 + ch*16));
        *(uint4*)(AhiB + off) = make_uint4(bpack(h[0],h[1]), bpack(h[2],h[3]),
                                           bpack(h[4],h[5]), bpack(h[6],h[7]));
        *(uint4*)(AloB + off) = make_uint4(bpack(l[0],l[1]), bpack(l[2],l[3]),
                                           bpack(l[4],l[5]), bpack(l[6],l[7]));
    }

    const int q = tid & 15;
    const int rsub = tid >> 4;

    for (int by = 0; by < 4; by++) {
        __syncthreads();
        {
            const uint4* sh = (const uint4*)(g_w3Hi + by*8192);
            const uint4* sl = (const uint4*)(g_w3Lo + by*8192);
            uint4* dh = (uint4*)(smraw + 24576);
            uint4* dl = (uint4*)(smraw + 32768);
            #pragma unroll
            for (int i = 0; i < 3; i++) {
                int o = tid + i*192;
                if (o < 512) { dh[o] = sh[o]; dl[o] = sl[o]; }
            }
        }
        if (tid < 16)
            *(float4*)&biasS[tid*4] = *(const float4*)&bfc[by*64 + tid*4];
        __syncthreads();

        float acc[8][4];
        #pragma unroll
        for (int j = 0; j < 8; j++) { acc[j][0]=0.f; acc[j][1]=0.f; acc[j][2]=0.f; acc[j][3]=0.f; }

        #pragma unroll
        for (int ks = 0; ks < 4; ks++) {
            const uint32_t kxa = (aCoff0 + ks*32) ^ xorv;
            const uint32_t kxb = (bCoff0 + ks*32) ^ xorv;
            uint32_t ah[4], al[4];
            ldsm_x4(aHiB0 + kxa, ah[0], ah[1], ah[2], ah[3]);
            ldsm_x4(aLoB0 + kxa, al[0], al[1], al[2], al[3]);
            #pragma unroll
            for (int jp = 0; jp < 4; jp++) {
                const uint32_t bb = bRow0 + (uint32_t)(jp*2048) + kxb;
                uint32_t bh0, bh1, bh2, bh3, bl0, bl1, bl2, bl3;
                ldsm_x4(bb,        bh0, bh1, bh2, bh3);
                ldsm_x4(bb + 8192, bl0, bl1, bl2, bl3);
                mma_bf16(acc[2*jp],   ah, bh0, bh1);
                mma_bf16(acc[2*jp],   ah, bl0, bl1);
                mma_bf16(acc[2*jp],   al, bh0, bh1);
                mma_bf16(acc[2*jp+1], ah, bh2, bh3);
                mma_bf16(acc[2*jp+1], ah, bl2, bl3);
                mma_bf16(acc[2*jp+1], al, bh2, bh3);
            }
        }

        __syncthreads();
        {
            const int rl0 = w*16 + g, rl1 = rl0 + 8;
            #pragma unroll
            for (int j = 0; j < 8; j++) {
                const int c = j*8 + 2*tig;
                __half2 h0 = __floats2half2_rn(acc[j][0], acc[j][1]);
                __half2 h1 = __floats2half2_rn(acc[j][2], acc[j][3]);
                *(__half2*)&CsH[rl0*68 + c] = h0;
                *(__half2*)&CsH[rl1*68 + c] = h1;
            }
        }
        __syncthreads();

        float s0=0.f,s1=0.f,s2=0.f,s3=0.f, q0=0.f,q1=0.f,q2=0.f,q3=0.f;
        #pragma unroll
        for (int it = 0; it < 8; it++) {
            const int r = it*12 + rsub;
            if (r < rem) {
                uint2 uc = *(const uint2*)&CsH[r*68 + q*4];
                float2 c01 = __half22float2(*(__half2*)&uc.x);
                float2 c23 = __half22float2(*(__half2*)&uc.y);
                uint2 u1 = *(const uint2*)&g_P1[(size_t)nS[r]*C2A + by*64 + q*4];
                uint2 u2 = *(const uint2*)&g_P2[(size_t)nbS[r]*C2A + by*64 + q*4];
                float2 p1a = __half22float2(*(__half2*)&u1.x);
                float2 p1b = __half22float2(*(__half2*)&u1.y);
                float2 p2a = __half22float2(*(__half2*)&u2.x);
                float2 p2b = __half22float2(*(__half2*)&u2.y);
                float4 bb = *(const float4*)&biasS[q*4];
                float4 v;
                v.x = c01.x + p1a.x + p2a.x + bb.x;
                v.y = c01.y + p1a.y + p2a.y + bb.y;
                v.z = c23.x + p1b.x + p2b.x + bb.z;
                v.w = c23.y + p1b.y + p2b.y + bb.w;
                __half2 h01 = __floats2half2_rn(v.x, v.y);
                __half2 h23 = __floats2half2_rn(v.z, v.w);
                *(uint2*)&g_gated[((size_t)(bx*96 + r))*C2A + by*64 + q*4] =
                    make_uint2(*(uint32_t*)&h01, *(uint32_t*)&h23);
                s0 += v.x; s1 += v.y; s2 += v.z; s3 += v.w;
                q0 += v.x*v.x; q1 += v.y*v.y; q2 += v.z*v.z; q3 += v.w*v.w;
            }
        }
        s0 += __shfl_xor_sync(0xffffffffu, s0, 16);
        s1 += __shfl_xor_sync(0xffffffffu, s1, 16);
        s2 += __shfl_xor_sync(0xffffffffu, s2, 16);
        s3 += __shfl_xor_sync(0xffffffffu, s3, 16);
        q0 += __shfl_xor_sync(0xffffffffu, q0, 16);
        q1 += __shfl_xor_sync(0xffffffffu, q1, 16);
        q2 += __shfl_xor_sync(0xffffffffu, q2, 16);
        q3 += __shfl_xor_sync(0xffffffffu, q3, 16);

        if (lane < 16) {
            float* d = &Red[w*64 + lane*4];
            d[0]=s0; d[1]=s1; d[2]=s2; d[3]=s3;
        }
        __syncthreads();
        if (tid < 64) {
            float ts = 0.f;
            #pragma unroll
            for (int w2 = 0; w2 < 6; w2++) ts += Red[w2*64 + tid];
            g_psum[(size_t)bx*C2A + by*64 + tid] = ts;
        }
        __syncthreads();
        if (lane < 16) {
            float* d = &Red[w*64 + lane*4];
            d[0]=q0; d[1]=q1; d[2]=q2; d[3]=q3;
        }
        __syncthreads();
        if (tid < 64) {
            float tq = 0.f;
            #pragma unroll
            for (int w2 = 0; w2 < 6; w2++) tq += Red[w2*64 + tid];
            g_psq[(size_t)bx*C2A + by*64 + tid] = tq;
        }
    }
}

// ---------------- K4: reduce partials -> column sums ------------------------
__global__ __launch_bounds__(256) void reduce_cols() {
    __shared__ float sm[256];
    const int b = blockIdx.x, tid = threadIdx.x;
    float s = 0.f;
    if (b < 256) {
        for (int i = tid; i < GTILES; i += 256) s += g_psum[(size_t)i * C2A + b];
    } else {
        int c = b - 256;
        for (int i = tid; i < GTILES; i += 256) s += g_psq[(size_t)i * C2A + c];
    }
    sm[tid] = s; __syncthreads();
    for (int off = 128; off > 0; off >>= 1) {
        if (tid < off) sm[tid] += sm[tid + off];
        __syncthreads();
    }
    if (tid == 0) {
        if (b < 256) g_colsum[b] = sm[0];
        else         g_colsq[b - 256] = sm[0];
    }
}

// ---------------- K5: BN1-apply + gate + per-atom sum (widened loads) -------
__global__ __launch_bounds__(256) void gate_apply(const float* __restrict__ gamma1,
                                                  const float* __restrict__ beta1) {
    __shared__ float s1s[C2A], s1b[C2A];
    __shared__ int sA[GA_ATOMS + 1];
    const int tid = threadIdx.x;
    const int bx = blockIdx.x;

    {
        float cnt = g_cntf;
        float mean = g_colsum[tid] / cnt;
        float var  = g_colsq[tid] / cnt - mean * mean;
        float sc   = rsqrtf(var + EPSV) * gamma1[tid];
        s1s[tid] = sc;
        s1b[tid] = beta1[tid] - mean * sc;
    }
    if (tid <= GA_ATOMS) {
        int i9 = (bx*GA_ATOMS + tid) * MNBR;
        sA[tid] = (i9 < NM) ? g_pos[i9] : g_nlive;
    }
    __syncthreads();

    const int c4 = (tid & 31) * 4;   // col quad
    const int ag = tid >> 5;         // 0..7
    const float sf0 = s1s[c4],   sf1 = s1s[c4+1], sf2 = s1s[c4+2], sf3 = s1s[c4+3];
    const float bf0 = s1b[c4],   bf1 = s1b[c4+1], bf2 = s1b[c4+2], bf3 = s1b[c4+3];
    const float sc0 = s1s[128+c4], sc1 = s1s[128+c4+1], sc2v = s1s[128+c4+2], sc3 = s1s[128+c4+3];
    const float bc0 = s1b[128+c4], bc1 = s1b[128+c4+1], bc2 = s1b[128+c4+2], bc3 = s1b[128+c4+3];

    #pragma unroll
    for (int aa = 0; aa < GA_ATOMS/8; aa++) {
        const int a = aa*8 + ag;
        const int atom = bx*GA_ATOMS + a;
        if (atom < NATOM) {
            const int start = sA[a], end = sA[a+1];
            float sx = 0.f, sy = 0.f, sz = 0.f, sw2 = 0.f;
            for (int row = start; row < end; row++) {
                uint2 uf  = *(const uint2*)&g_gated[(size_t)row*C2A + c4];
                uint2 ucv = *(const uint2*)&g_gated[(size_t)row*C2A + 128 + c4];
                float2 fa = __half22float2(*(__half2*)&uf.x);
                float2 fb = __half22float2(*(__half2*)&uf.y);
                float2 ca = __half22float2(*(__half2*)&ucv.x);
                float2 cb = __half22float2(*(__half2*)&ucv.y);
                sx  += fast_sigmoid(fa.x*sf0 + bf0) * fast_softplus(ca.x*sc0 + bc0);
                sy  += fast_sigmoid(fa.y*sf1 + bf1) * fast_softplus(ca.y*sc1 + bc1);
                sz  += fast_sigmoid(fb.x*sf2 + bf2) * fast_softplus(cb.x*sc2v + bc2);
                sw2 += fast_sigmoid(fb.y*sf3 + bf3) * fast_softplus(cb.y*sc3 + bc3);
            }
            *(float4*)&g_ns[(size_t)atom*AFEA + c4] = make_float4(sx, sy, sz, sw2);
        }
    }
}

// ---------------- K6: BN2 stats + affine ------------------------------------
__global__ __launch_bounds__(256) void reduce2(const float* __restrict__ gamma2,
                                               const float* __restrict__ beta2) {
    __shared__ float ss[256], sq[256];
    const int c = blockIdx.x, tid = threadIdx.x;
    float s = 0.f, q = 0.f;
    for (int r = tid; r < NATOM; r += 256) {
        float v = g_ns[(size_t)r * AFEA + c];
        s += v; q += v * v;
    }
    ss[tid] = s; sq[tid] = q; __syncthreads();
    for (int off = 128; off > 0; off >>= 1) {
        if (tid < off) { ss[tid] += ss[tid + off]; sq[tid] += sq[tid + off]; }
        __syncthreads();
    }
    if (tid == 0) {
        float mean = ss[0] / (float)NATOM;
        float var  = sq[0] / (float)NATOM - mean * mean;
        float sc   = rsqrtf(var + EPSV) * gamma2[c];
        g_scale2[c] = sc;
        g_shift2[c] = beta2[c] - mean * sc;
    }
}

// ---------------- K7: out = softplus(atom + BN2(nbr_sumed)) -----------------
__global__ __launch_bounds__(256) void out_k(const float* __restrict__ atom,
                                             float* __restrict__ out) {
    int i = blockIdx.x * 256 + threadIdx.x;
    if (i < NATOM * AFEA) {
        int c = i & 127;
        float v = atom[i] + g_ns[i] * g_scale2[c] + g_shift2[c];
        out[i] = fmaxf(v, 0.f) + __logf(1.f + __expf(-fabsf(v)));
    }
}

// ---------------- launch ----------------------------------------------------
extern "C" void kernel_launch(void* const* d_in, const int* in_sizes, int n_in,
                              void* d_out, int out_size) {
    const float* atom  = (const float*)d_in[0];
    const float* nbr   = (const float*)d_in[1];
    const int*   idx   = (const int*)  d_in[2];
    const float* mask  = (const float*)d_in[3];
    const float* W     = (const float*)d_in[4];
    const float* bfc   = (const float*)d_in[5];
    const float* g1    = (const float*)d_in[6];
    const float* b1    = (const float*)d_in[7];
    const float* g2    = (const float*)d_in[8];
    const float* b2    = (const float*)d_in[9];
    float* out = (float*)d_out;

    cudaFuncSetAttribute(gemm_gated_tc, cudaFuncAttributeMaxDynamicSharedMemorySize, SM_TOTAL);

    mega_split   <<<NSC + 6250 + 128 + 8, 256>>>(mask, atom, W);         // 0
    scan2        <<<1, 1024>>>();                                        // 1
    scan3_p12    <<<NSC + P12_BX*8, 256>>>(mask);                        // 2
    gemm_gated_tc<<<GTILES, 192, SM_TOTAL>>>(nbr, bfc, idx);             // 3 (profiled)
    reduce_cols  <<<512, 256>>>();                                       // 4
    gate_apply   <<<(NATOM + GA_ATOMS - 1)/GA_ATOMS, 256>>>(g1, b1);     // 5
    reduce2      <<<AFEA, 256>>>(g2, b2);                                // 6
    out_k        <<<(NATOM * AFEA + 255) / 256, 256>>>(atom, out);       // 7
}